// round 6
// baseline (speedup 1.0000x reference)
#include <cuda_runtime.h>

// Problem constants (fixed by the dataset shapes)
#define HWC   65536      // 256*256
#define BATCH 64
#define NATT  4096
#define MREP  2048

// One thread per corner.
// attract corners: B*N*4  = 1,048,576  (layout [B,N,4]   -> corner = tid&3)
// repel corners:   B*M*2*4= 1,048,576  (layout [B,M,2,4] -> corner = tid&3, box = (tid>>2)&1)
#define ATT_CORNERS (BATCH * NATT * 4)
#define REP_CORNERS (BATCH * MREP * 8)
#define ATT_BLOCKS  (ATT_CORNERS / 256)   // 4096
#define REP_BLOCKS  (REP_CORNERS / 256)   // 4096
#define TOT_BLOCKS  (ATT_BLOCKS + REP_BLOCKS)

// Accumulators: [0]=S_attract, [1]=N_attract, [2]=S_repel, [3]=N_repel.
// Zero-initialized at load; finalizing block re-zeros for graph-replay determinism.
__device__ double g_acc[4];
__device__ unsigned int g_done;

__device__ __forceinline__ float iou_f(float hA, float yA, float xA,
                                       float hB, float yB, float xB) {
    float areaA = hA * hA * 0.41f;
    float areaB = hB * hB * 0.41f;
    float y_min_max = fmaxf(yA - hA * 0.5f,         yB - hB * 0.5f);
    float x_min_max = fmaxf(xA - 0.41f * hA * 0.5f, xB - 0.41f * hB * 0.5f);
    float y_max_min = fminf(yA + hA * 0.5f,         yB + hB * 0.5f);
    float x_max_min = fminf(xA + 0.41f * hA * 0.5f, xB + 0.41f * hB * 0.5f);
    float I = fmaxf(y_max_min - y_min_max, 0.0f) * fmaxf(x_max_min - x_min_max, 0.0f);
    float U = areaA + areaB - I;
    return I / (U + 1e-6f);
}

// Sum over the 4 lanes of each quad (lane&~3 .. lane|3).
__device__ __forceinline__ float quad_sum(float v) {
    v += __shfl_xor_sync(0xFFFFFFFFu, v, 1);
    v += __shfl_xor_sync(0xFFFFFFFFu, v, 2);
    return v;
}

// Block-wide reduction of (v0, v1) -> 2 double atomics. blockDim.x == 256.
__device__ __forceinline__ void block_reduce2(float v0, float v1,
                                              double* acc0, double* acc1) {
    #pragma unroll
    for (int o = 16; o > 0; o >>= 1) {
        v0 += __shfl_down_sync(0xFFFFFFFFu, v0, o);
        v1 += __shfl_down_sync(0xFFFFFFFFu, v1, o);
    }
    __shared__ float s0[8], s1[8];
    int lane = threadIdx.x & 31;
    int warp = threadIdx.x >> 5;
    if (lane == 0) { s0[warp] = v0; s1[warp] = v1; }
    __syncthreads();
    if (warp == 0) {
        v0 = (lane < 8) ? s0[lane] : 0.0f;
        v1 = (lane < 8) ? s1[lane] : 0.0f;
        #pragma unroll
        for (int o = 4; o > 0; o >>= 1) {
            v0 += __shfl_down_sync(0x000000FFu, v0, o);
            v1 += __shfl_down_sync(0x000000FFu, v1, o);
        }
        if (lane == 0) {
            atomicAdd(acc0, (double)v0);
            atomicAdd(acc1, (double)v1);
        }
    }
}

__global__ __launch_bounds__(256)
void fused_iou_loss_kernel(const float* __restrict__ oh,
                           const float* __restrict__ ooff,
                           const float* __restrict__ pre_off,
                           const int*   __restrict__ attract,
                           const int*   __restrict__ repel,
                           const unsigned char* __restrict__ mask_att,
                           const unsigned char* __restrict__ mask_rep,
                           float* __restrict__ out) {
    // OFFSETS = [[0,0],[1,0],[0,1],[1,1]]: ch0 += {0,1,0,1}, ch1 += {0,0,1,1}
    if (blockIdx.x < ATT_BLOCKS) {
        // -------- attract: one thread per corner, 3 gathers + quad shuffles --------
        int c = blockIdx.x * 256 + threadIdx.x;   // [0, 2^20)
        int b = c >> 14;                          // / (NATT*4)
        int k = c & 3;                            // corner

        int idx = __ldg(attract + c);
        unsigned char msk = mask_att[c];

        const float* ohb = oh   + ((size_t)b << 16);
        const float* o0b = ooff + ((size_t)b << 17);
        const float* o1b = o0b + HWC;

        float h  = __ldg(ohb + idx);
        float oy = __ldg(o0b + idx) + (float)(k & 1);         // OFFSETS[k][0]
        float ox = __ldg(o1b + idx) + (float)((k >> 1) & 1);  // OFFSETS[k][1]

        float hm  = quad_sum(h)  * 0.25f;
        float oym = quad_sum(oy) * 0.25f;
        float oxm = quad_sum(ox) * 0.25f;
        float hB = expf(hm);

        float lsum = 0.f, cnt = 0.f;
        if (msk) {
            lsum = 1.0f - iou_f(expf(h), oy, ox, hB, oym, oxm);
            cnt  = 1.0f;
        }
        block_reduce2(lsum, cnt, &g_acc[0], &g_acc[1]);
    } else {
        // -------- repel: one thread per corner, 3 gathers + quad/octet shuffles --------
        int c = (blockIdx.x - ATT_BLOCKS) * 256 + threadIdx.x;  // [0, 2^20)
        int b = c >> 14;                                        // / (MREP*8)
        int item = c >> 3;                                      // b*MREP + m
        int boxj = (c >> 2) & 1;

        int idx = __ldg(repel + c);

        const float* ohb = oh   + ((size_t)b << 16);
        const float* o0b = ooff + ((size_t)b << 17);
        const float* o1b = o0b + HWC;

        float h  = __ldg(ohb + idx);
        float oy = __ldg(o0b + idx);
        float ox = __ldg(o1b + idx);

        // per-box means (mean of off + OFFSETS == mean + 0.5 per channel)
        float hm = quad_sum(h)  * 0.25f;
        float y  = quad_sum(oy) * 0.25f + 0.5f;
        float x  = quad_sum(ox) * 0.25f + 0.5f;

        // box 1 gets pre_off added to its mean (broadcast load: 8 lanes same addr)
        float2 po = reinterpret_cast<const float2*>(pre_off)[item];
        if (boxj) { y += po.x; x += po.y; }

        float hE = expf(hm);
        // exchange with the partner box (lanes xor 4); IoU is symmetric
        float hO = __shfl_xor_sync(0xFFFFFFFFu, hE, 4);
        float yO = __shfl_xor_sync(0xFFFFFFFFu, y,  4);
        float xO = __shfl_xor_sync(0xFFFFFFFFu, x,  4);

        float v = iou_f(hE, y, x, hO, yO, xO);

        float lsum = 0.f, cnt = 0.f;
        if ((c & 7) == 0 && mask_rep[item]) { lsum = v; cnt = 1.0f; }
        block_reduce2(lsum, cnt, &g_acc[2], &g_acc[3]);
    }

    // ---------------- last-block finalize + reset ----------------
    __threadfence();
    __shared__ bool s_last;
    if (threadIdx.x == 0) {
        unsigned int ticket = atomicAdd(&g_done, 1u);
        s_last = (ticket == (unsigned int)(TOT_BLOCKS - 1));
    }
    __syncthreads();
    if (s_last && threadIdx.x == 0) {
        double sa = g_acc[0], na = g_acc[1];
        double sr = g_acc[2], nr = g_acc[3];
        out[0] = (float)(sa / (na + 1e-4) + sr / (nr + 1e-4));
        g_acc[0] = 0.0; g_acc[1] = 0.0; g_acc[2] = 0.0; g_acc[3] = 0.0;
        __threadfence();
        g_done = 0u;
    }
}

extern "C" void kernel_launch(void* const* d_in, const int* in_sizes, int n_in,
                              void* d_out, int out_size) {
    const float* output_h    = (const float*)d_in[0];  // [64,1,256,256]
    const float* output_off  = (const float*)d_in[1];  // [64,2,256,256]
    // d_in[2], d_in[3]: target_h / target_off — unused by the reference
    const float* pre_off     = (const float*)d_in[4];  // [64,2048,2]
    const int*   attract     = (const int*)  d_in[5];  // [64,4096,4]
    const int*   repel       = (const int*)  d_in[6];  // [64,2048,2,4]
    const unsigned char* mask_attract = (const unsigned char*)d_in[7];  // [64,4096,4] bool
    const unsigned char* mask_repel   = (const unsigned char*)d_in[8];  // [64,2048,1] bool
    float* out = (float*)d_out;

    fused_iou_loss_kernel<<<TOT_BLOCKS, 256>>>(
        output_h, output_off, pre_off, attract, repel,
        mask_attract, mask_repel, out);
}

// round 7
// speedup vs baseline: 1.8422x; 1.8422x over previous
#include <cuda_runtime.h>

// Problem constants (fixed by the dataset shapes)
#define HWC   65536      // 256*256
#define BATCH 64
#define NATT  4096
#define MREP  2048

// Uniform work: every thread performs exactly 12 gathers.
// attract: one item/thread            -> B*N   = 262144 threads
// repel:   one box/thread (pair=2 lanes) -> B*M*2 = 262144 threads
#define ATT_THREADS (BATCH * NATT)
#define REP_THREADS (BATCH * MREP * 2)
#define TPB         128
#define ATT_BLOCKS  (ATT_THREADS / TPB)   // 2048
#define REP_BLOCKS  (REP_THREADS / TPB)   // 2048
#define TOT_BLOCKS  (ATT_BLOCKS + REP_BLOCKS)

// Accumulators: [0]=S_attract, [1]=N_attract, [2]=S_repel, [3]=N_repel.
// Zero-initialized at load; finalizing block re-zeros for graph-replay determinism.
__device__ double g_acc[4];
__device__ unsigned int g_done;

__device__ __forceinline__ float iou_f(float hA, float yA, float xA,
                                       float hB, float yB, float xB) {
    float areaA = hA * hA * 0.41f;
    float areaB = hB * hB * 0.41f;
    float y_min_max = fmaxf(yA - hA * 0.5f,         yB - hB * 0.5f);
    float x_min_max = fmaxf(xA - 0.41f * hA * 0.5f, xB - 0.41f * hB * 0.5f);
    float y_max_min = fminf(yA + hA * 0.5f,         yB + hB * 0.5f);
    float x_max_min = fminf(xA + 0.41f * hA * 0.5f, xB + 0.41f * hB * 0.5f);
    float I = fmaxf(y_max_min - y_min_max, 0.0f) * fmaxf(x_max_min - x_min_max, 0.0f);
    float U = areaA + areaB - I;
    return I / (U + 1e-6f);
}

// Block-wide reduction of (v0, v1) -> 2 double atomics. blockDim.x == 128.
__device__ __forceinline__ void block_reduce2(float v0, float v1,
                                              double* acc0, double* acc1) {
    #pragma unroll
    for (int o = 16; o > 0; o >>= 1) {
        v0 += __shfl_down_sync(0xFFFFFFFFu, v0, o);
        v1 += __shfl_down_sync(0xFFFFFFFFu, v1, o);
    }
    __shared__ float s0[4], s1[4];
    int lane = threadIdx.x & 31;
    int warp = threadIdx.x >> 5;
    if (lane == 0) { s0[warp] = v0; s1[warp] = v1; }
    __syncthreads();
    if (warp == 0) {
        v0 = (lane < 4) ? s0[lane] : 0.0f;
        v1 = (lane < 4) ? s1[lane] : 0.0f;
        v0 += __shfl_down_sync(0x0000000Fu, v0, 2);
        v1 += __shfl_down_sync(0x0000000Fu, v1, 2);
        v0 += __shfl_down_sync(0x0000000Fu, v0, 1);
        v1 += __shfl_down_sync(0x0000000Fu, v1, 1);
        if (lane == 0) {
            atomicAdd(acc0, (double)v0);
            atomicAdd(acc1, (double)v1);
        }
    }
}

__global__ __launch_bounds__(TPB)
void fused_iou_loss_kernel(const float* __restrict__ oh,
                           const float* __restrict__ ooff,
                           const float* __restrict__ pre_off,
                           const int*   __restrict__ attract,
                           const int*   __restrict__ repel,
                           const unsigned char* __restrict__ mask_att,
                           const unsigned char* __restrict__ mask_rep,
                           float* __restrict__ out) {
    // OFFSETS = [[0,0],[1,0],[0,1],[1,1]]: ch0 += {0,1,0,1}, ch1 += {0,0,1,1}
    if (blockIdx.x < ATT_BLOCKS) {
        // -------- attract: one item per thread, 12 gathers --------
        int gid = blockIdx.x * TPB + threadIdx.x;   // b*NATT + n
        int b   = gid >> 12;                        // / 4096

        int4 idx4 = reinterpret_cast<const int4*>(attract)[gid];
        unsigned int m4 = reinterpret_cast<const unsigned int*>(mask_att)[gid];

        const float* ohb = oh   + ((size_t)b << 16);
        const float* o0b = ooff + ((size_t)b << 17);
        const float* o1b = o0b + HWC;

        int ind[4] = {idx4.x, idx4.y, idx4.z, idx4.w};
        float h[4], o0[4], o1[4];
        #pragma unroll
        for (int k = 0; k < 4; k++) {
            h[k]  = __ldg(ohb + ind[k]);
            o0[k] = __ldg(o0b + ind[k]);
            o1[k] = __ldg(o1b + ind[k]);
        }

        const float kx[4] = {0.f, 1.f, 0.f, 1.f};
        const float ky[4] = {0.f, 0.f, 1.f, 1.f};

        float hm = 0.f, o0m = 0.f, o1m = 0.f;
        #pragma unroll
        for (int k = 0; k < 4; k++) {
            o0[k] += kx[k];
            o1[k] += ky[k];
            hm  += h[k];
            o0m += o0[k];
            o1m += o1[k];
        }
        hm *= 0.25f; o0m *= 0.25f; o1m *= 0.25f;
        float hB = expf(hm);

        float lsum = 0.f, cnt = 0.f;
        #pragma unroll
        for (int k = 0; k < 4; k++) {
            if ((m4 >> (8 * k)) & 0xFFu) {
                lsum += 1.0f - iou_f(expf(h[k]), o0[k], o1[k], hB, o0m, o1m);
                cnt  += 1.0f;
            }
        }
        block_reduce2(lsum, cnt, &g_acc[0], &g_acc[1]);
    } else {
        // -------- repel: one BOX per thread, 12 gathers; pair via shfl_xor(1) --------
        int u    = (blockIdx.x - ATT_BLOCKS) * TPB + threadIdx.x;  // [0, B*M*2)
        int item = u >> 1;                                         // b*MREP + m
        int boxj = u & 1;
        int b    = u >> 12;                                        // / (MREP*2)

        // repel[b][m][j][0..3] -> int4 at flat offset u (coalesced)
        int4 q = reinterpret_cast<const int4*>(repel)[u];

        const float* ohb = oh   + ((size_t)b << 16);
        const float* o0b = ooff + ((size_t)b << 17);
        const float* o1b = o0b + HWC;

        int ind[4] = {q.x, q.y, q.z, q.w};
        float hs = 0.f, sy = 0.f, sx = 0.f;
        #pragma unroll
        for (int k = 0; k < 4; k++) {
            hs += __ldg(ohb + ind[k]);
            sy += __ldg(o0b + ind[k]);
            sx += __ldg(o1b + ind[k]);
        }

        // mean of (off + OFFSETS): OFFSETS contributes +0.5 per channel
        float hm = hs * 0.25f;
        float y  = sy * 0.25f + 0.5f;
        float x  = sx * 0.25f + 0.5f;

        // box 1 mean gets pre_off (both lanes of the pair load the same float2)
        float2 po = reinterpret_cast<const float2*>(pre_off)[item];
        if (boxj) { y += po.x; x += po.y; }

        float hE = expf(hm);
        // exchange mean boxes with the partner lane (IoU symmetric)
        float hO = __shfl_xor_sync(0xFFFFFFFFu, hE, 1);
        float yO = __shfl_xor_sync(0xFFFFFFFFu, y,  1);
        float xO = __shfl_xor_sync(0xFFFFFFFFu, x,  1);

        float v = iou_f(hE, y, x, hO, yO, xO);

        float lsum = 0.f, cnt = 0.f;
        if (boxj == 0 && mask_rep[item]) { lsum = v; cnt = 1.0f; }
        block_reduce2(lsum, cnt, &g_acc[2], &g_acc[3]);
    }

    // ---------------- last-block finalize + reset ----------------
    __threadfence();
    __shared__ bool s_last;
    if (threadIdx.x == 0) {
        unsigned int ticket = atomicAdd(&g_done, 1u);
        s_last = (ticket == (unsigned int)(TOT_BLOCKS - 1));
    }
    __syncthreads();
    if (s_last && threadIdx.x == 0) {
        double sa = g_acc[0], na = g_acc[1];
        double sr = g_acc[2], nr = g_acc[3];
        out[0] = (float)(sa / (na + 1e-4) + sr / (nr + 1e-4));
        g_acc[0] = 0.0; g_acc[1] = 0.0; g_acc[2] = 0.0; g_acc[3] = 0.0;
        __threadfence();
        g_done = 0u;
    }
}

extern "C" void kernel_launch(void* const* d_in, const int* in_sizes, int n_in,
                              void* d_out, int out_size) {
    const float* output_h    = (const float*)d_in[0];  // [64,1,256,256]
    const float* output_off  = (const float*)d_in[1];  // [64,2,256,256]
    // d_in[2], d_in[3]: target_h / target_off — unused by the reference
    const float* pre_off     = (const float*)d_in[4];  // [64,2048,2]
    const int*   attract     = (const int*)  d_in[5];  // [64,4096,4]
    const int*   repel       = (const int*)  d_in[6];  // [64,2048,2,4]
    const unsigned char* mask_attract = (const unsigned char*)d_in[7];  // [64,4096,4] bool
    const unsigned char* mask_repel   = (const unsigned char*)d_in[8];  // [64,2048,1] bool
    float* out = (float*)d_out;

    fused_iou_loss_kernel<<<TOT_BLOCKS, TPB>>>(
        output_h, output_off, pre_off, attract, repel,
        mask_attract, mask_repel, out);
}

// round 9
// speedup vs baseline: 2.0595x; 1.1179x over previous
#include <cuda_runtime.h>

// Problem constants (fixed by the dataset shapes)
#define HWC   65536      // 256*256
#define BATCH 64
#define NATT  4096
#define MREP  2048

// Balanced single-wave grid (R3 schedule): every thread does exactly 24 gathers.
// blocks [0, REP_BLOCKS): 1 repel item/thread (24 loads)
// blocks [REP_BLOCKS, TOT_BLOCKS): 2 attract items/thread (2x12 loads)
#define REP_BLOCKS ((BATCH * MREP) / 256)        // 512
#define ATT_BLOCKS ((BATCH * NATT) / (2 * 256))  // 512
#define TOT_BLOCKS (REP_BLOCKS + ATT_BLOCKS)     // 1024

// Accumulators: [0]=S_attract, [1]=N_attract, [2]=S_repel, [3]=N_repel.
// Zero-initialized at load; finalizing block re-zeros for graph-replay determinism.
__device__ double g_acc[4];
__device__ unsigned int g_done;

// ---- cache-policy helpers (createpolicy + cache_hint form; the bare
// .L2::evict_last qualifier is rejected by ptxas for scalar loads) ----
__device__ __forceinline__ unsigned long long mk_policy_keep() {
    unsigned long long p;
    asm("createpolicy.fractional.L2::evict_last.b64 %0, 1.0;" : "=l"(p));
    return p;
}
__device__ __forceinline__ unsigned long long mk_policy_stream() {
    unsigned long long p;
    asm("createpolicy.fractional.L2::evict_first.b64 %0, 1.0;" : "=l"(p));
    return p;
}
// Maps (random-gathered, reused across graph replays): keep in L2.
__device__ __forceinline__ float ld_keep(const float* p, unsigned long long pol) {
    float v;
    asm volatile("ld.global.nc.L2::cache_hint.f32 %0, [%1], %2;"
                 : "=f"(v) : "l"(p), "l"(pol));
    return v;
}
// Streaming data (indices/masks/pre_off, touched once): evict first.
__device__ __forceinline__ int4 ld_stream_int4(const int4* p, unsigned long long pol) {
    int4 v;
    asm volatile("ld.global.nc.L2::cache_hint.v4.s32 {%0,%1,%2,%3}, [%4], %5;"
                 : "=r"(v.x), "=r"(v.y), "=r"(v.z), "=r"(v.w) : "l"(p), "l"(pol));
    return v;
}
__device__ __forceinline__ uint2 ld_stream_u2(const uint2* p, unsigned long long pol) {
    uint2 v;
    asm volatile("ld.global.nc.L2::cache_hint.v2.u32 {%0,%1}, [%2], %3;"
                 : "=r"(v.x), "=r"(v.y) : "l"(p), "l"(pol));
    return v;
}
__device__ __forceinline__ float2 ld_stream_f2(const float2* p, unsigned long long pol) {
    float2 v;
    asm volatile("ld.global.nc.L2::cache_hint.v2.f32 {%0,%1}, [%2], %3;"
                 : "=f"(v.x), "=f"(v.y) : "l"(p), "l"(pol));
    return v;
}
__device__ __forceinline__ unsigned int ld_stream_u8(const unsigned char* p,
                                                     unsigned long long pol) {
    unsigned short v;
    asm volatile("ld.global.nc.L2::cache_hint.u8 %0, [%1], %2;"
                 : "=h"(v) : "l"(p), "l"(pol));
    return (unsigned int)v;
}

__device__ __forceinline__ float iou_f(float hA, float yA, float xA,
                                       float hB, float yB, float xB) {
    float areaA = hA * hA * 0.41f;
    float areaB = hB * hB * 0.41f;
    float y_min_max = fmaxf(yA - hA * 0.5f,         yB - hB * 0.5f);
    float x_min_max = fmaxf(xA - 0.41f * hA * 0.5f, xB - 0.41f * hB * 0.5f);
    float y_max_min = fminf(yA + hA * 0.5f,         yB + hB * 0.5f);
    float x_max_min = fminf(xA + 0.41f * hA * 0.5f, xB + 0.41f * hB * 0.5f);
    float I = fmaxf(y_max_min - y_min_max, 0.0f) * fmaxf(x_max_min - x_min_max, 0.0f);
    float U = areaA + areaB - I;
    return I / (U + 1e-6f);
}

// Block-wide reduction of (v0, v1) -> 2 double atomics. blockDim.x == 256.
__device__ __forceinline__ void block_reduce2(float v0, float v1,
                                              double* acc0, double* acc1) {
    #pragma unroll
    for (int o = 16; o > 0; o >>= 1) {
        v0 += __shfl_down_sync(0xFFFFFFFFu, v0, o);
        v1 += __shfl_down_sync(0xFFFFFFFFu, v1, o);
    }
    __shared__ float s0[8], s1[8];
    int lane = threadIdx.x & 31;
    int warp = threadIdx.x >> 5;
    if (lane == 0) { s0[warp] = v0; s1[warp] = v1; }
    __syncthreads();
    if (warp == 0) {
        v0 = (lane < 8) ? s0[lane] : 0.0f;
        v1 = (lane < 8) ? s1[lane] : 0.0f;
        #pragma unroll
        for (int o = 4; o > 0; o >>= 1) {
            v0 += __shfl_down_sync(0x000000FFu, v0, o);
            v1 += __shfl_down_sync(0x000000FFu, v1, o);
        }
        if (lane == 0) {
            atomicAdd(acc0, (double)v0);
            atomicAdd(acc1, (double)v1);
        }
    }
}

// One attract item: 12 gathers + per-corner IoU against the mean box.
__device__ __forceinline__ void attract_item(int gid,
                                             const float* __restrict__ oh,
                                             const float* __restrict__ ooff,
                                             const int4 idx4, unsigned int m4,
                                             unsigned long long pol_keep,
                                             float& lsum, float& cnt) {
    int b = gid >> 12;  // / 4096
    const float* ohb = oh   + ((size_t)b << 16);
    const float* o0b = ooff + ((size_t)b << 17);
    const float* o1b = o0b + HWC;

    int ind[4] = {idx4.x, idx4.y, idx4.z, idx4.w};
    float h[4], o0[4], o1[4];
    #pragma unroll
    for (int k = 0; k < 4; k++) {
        h[k]  = ld_keep(ohb + ind[k], pol_keep);
        o0[k] = ld_keep(o0b + ind[k], pol_keep);
        o1[k] = ld_keep(o1b + ind[k], pol_keep);
    }

    // OFFSETS = [[0,0],[1,0],[0,1],[1,1]] added to (o0, o1)
    const float kx[4] = {0.f, 1.f, 0.f, 1.f};
    const float ky[4] = {0.f, 0.f, 1.f, 1.f};

    float hm = 0.f, o0m = 0.f, o1m = 0.f;
    #pragma unroll
    for (int k = 0; k < 4; k++) {
        o0[k] += kx[k];
        o1[k] += ky[k];
        hm  += h[k];
        o0m += o0[k];
        o1m += o1[k];
    }
    hm *= 0.25f; o0m *= 0.25f; o1m *= 0.25f;
    float hB = __expf(hm);

    #pragma unroll
    for (int k = 0; k < 4; k++) {
        if ((m4 >> (8 * k)) & 0xFFu) {
            lsum += 1.0f - iou_f(__expf(h[k]), o0[k], o1[k], hB, o0m, o1m);
            cnt  += 1.0f;
        }
    }
}

__global__ __launch_bounds__(256, 8)
void fused_iou_loss_kernel(const float* __restrict__ oh,
                           const float* __restrict__ ooff,
                           const float* __restrict__ pre_off,
                           const int*   __restrict__ attract,
                           const int*   __restrict__ repel,
                           const unsigned char* __restrict__ mask_att,
                           const unsigned char* __restrict__ mask_rep,
                           float* __restrict__ out) {
    unsigned long long pol_keep   = mk_policy_keep();
    unsigned long long pol_stream = mk_policy_stream();

    if (blockIdx.x < REP_BLOCKS) {
        // ------------- repel branch: one thread per (b, m), 24 gathers -------------
        int gid = blockIdx.x * 256 + threadIdx.x;   // b*MREP + m
        int b   = gid >> 11;                        // / 2048

        const int4* rp = reinterpret_cast<const int4*>(repel) + (size_t)gid * 2;
        int4 i0 = ld_stream_int4(rp,     pol_stream);
        int4 i1 = ld_stream_int4(rp + 1, pol_stream);

        const float* ohb = oh   + ((size_t)b << 16);
        const float* o0b = ooff + ((size_t)b << 17);
        const float* o1b = o0b + HWC;

        int ind[8] = {i0.x, i0.y, i0.z, i0.w, i1.x, i1.y, i1.z, i1.w};
        float hs[8], a0[8], a1[8];
        #pragma unroll
        for (int k = 0; k < 8; k++) {
            hs[k] = ld_keep(ohb + ind[k], pol_keep);
            a0[k] = ld_keep(o0b + ind[k], pol_keep);
            a1[k] = ld_keep(o1b + ind[k], pol_keep);
        }

        float hmean[2], y[2], x[2];
        #pragma unroll
        for (int j = 0; j < 2; j++) {
            float hsum = 0.f, s0 = 0.f, s1 = 0.f;
            #pragma unroll
            for (int k = 0; k < 4; k++) {
                hsum += hs[j * 4 + k];
                s0   += a0[j * 4 + k];
                s1   += a1[j * 4 + k];
            }
            hmean[j] = hsum * 0.25f;
            // mean of (off + OFFSETS): OFFSETS contributes +0.5 per channel
            y[j] = s0 * 0.25f + 0.5f;
            x[j] = s1 * 0.25f + 0.5f;
        }
        float2 po = ld_stream_f2(reinterpret_cast<const float2*>(pre_off) + gid,
                                 pol_stream);
        y[1] += po.x;
        x[1] += po.y;

        float v = iou_f(__expf(hmean[0]), y[0], x[0],
                        __expf(hmean[1]), y[1], x[1]);

        float lsum = 0.f, cnt = 0.f;
        if (ld_stream_u8(mask_rep + gid, pol_stream)) { lsum = v; cnt = 1.0f; }
        block_reduce2(lsum, cnt, &g_acc[2], &g_acc[3]);
    } else {
        // ----------- attract branch: two items per thread, 2x12 gathers -----------
        int w = (blockIdx.x - REP_BLOCKS) * 256 + threadIdx.x;  // [0, B*NATT/2)
        int gid0 = 2 * w;                                        // even item
        const int4* ap = reinterpret_cast<const int4*>(attract) + gid0;
        int4 idxA = ld_stream_int4(ap,     pol_stream);
        int4 idxB = ld_stream_int4(ap + 1, pol_stream);
        uint2 m2 = ld_stream_u2(reinterpret_cast<const uint2*>(mask_att) + w,
                                pol_stream);

        float lsum = 0.f, cnt = 0.f;
        attract_item(gid0,     oh, ooff, idxA, m2.x, pol_keep, lsum, cnt);
        attract_item(gid0 + 1, oh, ooff, idxB, m2.y, pol_keep, lsum, cnt);
        block_reduce2(lsum, cnt, &g_acc[0], &g_acc[1]);
    }

    // ---------------- last-block finalize + reset ----------------
    __threadfence();
    __shared__ bool s_last;
    if (threadIdx.x == 0) {
        unsigned int ticket = atomicAdd(&g_done, 1u);
        s_last = (ticket == (unsigned int)(TOT_BLOCKS - 1));
    }
    __syncthreads();
    if (s_last && threadIdx.x == 0) {
        double sa = g_acc[0], na = g_acc[1];
        double sr = g_acc[2], nr = g_acc[3];
        out[0] = (float)(sa / (na + 1e-4) + sr / (nr + 1e-4));
        g_acc[0] = 0.0; g_acc[1] = 0.0; g_acc[2] = 0.0; g_acc[3] = 0.0;
        __threadfence();
        g_done = 0u;
    }
}

extern "C" void kernel_launch(void* const* d_in, const int* in_sizes, int n_in,
                              void* d_out, int out_size) {
    const float* output_h    = (const float*)d_in[0];  // [64,1,256,256]
    const float* output_off  = (const float*)d_in[1];  // [64,2,256,256]
    // d_in[2], d_in[3]: target_h / target_off — unused by the reference
    const float* pre_off     = (const float*)d_in[4];  // [64,2048,2]
    const int*   attract     = (const int*)  d_in[5];  // [64,4096,4]
    const int*   repel       = (const int*)  d_in[6];  // [64,2048,2,4]
    const unsigned char* mask_attract = (const unsigned char*)d_in[7];  // [64,4096,4] bool
    const unsigned char* mask_repel   = (const unsigned char*)d_in[8];  // [64,2048,1] bool
    float* out = (float*)d_out;

    fused_iou_loss_kernel<<<TOT_BLOCKS, 256>>>(
        output_h, output_off, pre_off, attract, repel,
        mask_attract, mask_repel, out);
}

// round 10
// speedup vs baseline: 2.3458x; 1.1390x over previous
#include <cuda_runtime.h>
#include <cuda_fp16.h>

// Problem constants (fixed by the dataset shapes)
#define HWC   65536      // 256*256
#define BATCH 64
#define NATT  4096
#define MREP  2048
#define NPIX  (BATCH * HWC)                      // 4,194,304

#define PACK_BLOCKS (NPIX / (2 * 256))           // 8192 (2 pixels/thread)

// Gather grid: R3's balanced schedule, 24 corner-gathers per thread.
#define REP_BLOCKS ((BATCH * MREP) / 256)        // 512
#define ATT_BLOCKS ((BATCH * NATT) / (2 * 256))  // 512
#define TOT_BLOCKS (REP_BLOCKS + ATT_BLOCKS)     // 1024

// 32 MiB packed maps: per pixel {h, off_y, off_x, 0} as 4 x fp16 (8 bytes).
// One 8B gather = ONE L1tex wavefront per corner (vs 3 scattered 4B loads).
__device__ __align__(16) uint2 g_pack[NPIX];

// Accumulators: [0]=S_attract, [1]=N_attract, [2]=S_repel, [3]=N_repel.
// Zero-initialized at load; finalizing block re-zeros for graph-replay determinism.
__device__ double g_acc[4];
__device__ unsigned int g_done;

// ---------------------------------------------------------------------------
// Pass 1: coalesced pack, 2 pixels per thread.
// ---------------------------------------------------------------------------
__device__ __forceinline__ unsigned int pack2h(float a, float b) {
    __half2 h = __floats2half2_rn(a, b);
    return *reinterpret_cast<unsigned int*>(&h);
}

__global__ __launch_bounds__(256)
void pack_kernel(const float* __restrict__ oh, const float* __restrict__ ooff) {
    int t = blockIdx.x * 256 + threadIdx.x;  // [0, NPIX/2)
    int p = t * 2;
    int b = p >> 16;
    int i = p & (HWC - 1);
    const float* base = ooff + ((size_t)b << 17);
    float2 h2 = __ldg(reinterpret_cast<const float2*>(oh + p));
    float2 y2 = __ldg(reinterpret_cast<const float2*>(base + i));
    float2 x2 = __ldg(reinterpret_cast<const float2*>(base + HWC + i));
    uint4 o;
    o.x = pack2h(h2.x, y2.x);
    o.y = pack2h(x2.x, 0.0f);
    o.z = pack2h(h2.y, y2.y);
    o.w = pack2h(x2.y, 0.0f);
    *reinterpret_cast<uint4*>(&g_pack[p]) = o;   // 16B store, 2 pixels
}

// ---------------------------------------------------------------------------
// Pass 2: gathers + IoU + reduction.
// ---------------------------------------------------------------------------
__device__ __forceinline__ float3 fetch_corner(const uint2* __restrict__ pk, int idx) {
    uint2 v = __ldg(pk + idx);
    __half2 ab = *reinterpret_cast<__half2*>(&v.x);
    __half2 cd = *reinterpret_cast<__half2*>(&v.y);
    float2 f0 = __half22float2(ab);
    float2 f1 = __half22float2(cd);
    return make_float3(f0.x, f0.y, f1.x);   // h, oy, ox
}

__device__ __forceinline__ float iou_f(float hA, float yA, float xA,
                                       float hB, float yB, float xB) {
    float areaA = hA * hA * 0.41f;
    float areaB = hB * hB * 0.41f;
    float y_min_max = fmaxf(yA - hA * 0.5f,         yB - hB * 0.5f);
    float x_min_max = fmaxf(xA - 0.41f * hA * 0.5f, xB - 0.41f * hB * 0.5f);
    float y_max_min = fminf(yA + hA * 0.5f,         yB + hB * 0.5f);
    float x_max_min = fminf(xA + 0.41f * hA * 0.5f, xB + 0.41f * hB * 0.5f);
    float I = fmaxf(y_max_min - y_min_max, 0.0f) * fmaxf(x_max_min - x_min_max, 0.0f);
    float U = areaA + areaB - I;
    return I / (U + 1e-6f);
}

// Block-wide reduction of (v0, v1) -> 2 double atomics. blockDim.x == 256.
__device__ __forceinline__ void block_reduce2(float v0, float v1,
                                              double* acc0, double* acc1) {
    #pragma unroll
    for (int o = 16; o > 0; o >>= 1) {
        v0 += __shfl_down_sync(0xFFFFFFFFu, v0, o);
        v1 += __shfl_down_sync(0xFFFFFFFFu, v1, o);
    }
    __shared__ float s0[8], s1[8];
    int lane = threadIdx.x & 31;
    int warp = threadIdx.x >> 5;
    if (lane == 0) { s0[warp] = v0; s1[warp] = v1; }
    __syncthreads();
    if (warp == 0) {
        v0 = (lane < 8) ? s0[lane] : 0.0f;
        v1 = (lane < 8) ? s1[lane] : 0.0f;
        #pragma unroll
        for (int o = 4; o > 0; o >>= 1) {
            v0 += __shfl_down_sync(0x000000FFu, v0, o);
            v1 += __shfl_down_sync(0x000000FFu, v1, o);
        }
        if (lane == 0) {
            atomicAdd(acc0, (double)v0);
            atomicAdd(acc1, (double)v1);
        }
    }
}

// One attract item: 4 packed gathers + per-corner IoU against the mean box.
__device__ __forceinline__ void attract_item(const uint2* __restrict__ pk,
                                             const int4 idx4, unsigned int m4,
                                             float& lsum, float& cnt) {
    int ind[4] = {idx4.x, idx4.y, idx4.z, idx4.w};
    float3 c[4];
    #pragma unroll
    for (int k = 0; k < 4; k++) c[k] = fetch_corner(pk, ind[k]);

    // OFFSETS = [[0,0],[1,0],[0,1],[1,1]] added to (oy, ox)
    const float kx[4] = {0.f, 1.f, 0.f, 1.f};
    const float ky[4] = {0.f, 0.f, 1.f, 1.f};

    float hm = 0.f, oym = 0.f, oxm = 0.f;
    float cy[4], cx[4];
    #pragma unroll
    for (int k = 0; k < 4; k++) {
        cy[k] = c[k].y + kx[k];
        cx[k] = c[k].z + ky[k];
        hm  += c[k].x;
        oym += cy[k];
        oxm += cx[k];
    }
    hm *= 0.25f; oym *= 0.25f; oxm *= 0.25f;
    float hB = __expf(hm);

    #pragma unroll
    for (int k = 0; k < 4; k++) {
        if ((m4 >> (8 * k)) & 0xFFu) {
            lsum += 1.0f - iou_f(__expf(c[k].x), cy[k], cx[k], hB, oym, oxm);
            cnt  += 1.0f;
        }
    }
}

__global__ __launch_bounds__(256, 8)
void gather_kernel(const float* __restrict__ pre_off,
                   const int*   __restrict__ attract,
                   const int*   __restrict__ repel,
                   const unsigned char* __restrict__ mask_att,
                   const unsigned char* __restrict__ mask_rep,
                   float* __restrict__ out) {
    if (blockIdx.x < REP_BLOCKS) {
        // ------------- repel: one thread per (b, m), 8 packed gathers -------------
        int gid = blockIdx.x * 256 + threadIdx.x;   // b*MREP + m
        int b   = gid >> 11;                        // / 2048
        const uint2* pk = g_pack + ((size_t)b << 16);

        const int4* rp = reinterpret_cast<const int4*>(repel) + (size_t)gid * 2;
        int4 i0 = __ldg(rp);
        int4 i1 = __ldg(rp + 1);
        int ind[8] = {i0.x, i0.y, i0.z, i0.w, i1.x, i1.y, i1.z, i1.w};

        float3 c[8];
        #pragma unroll
        for (int k = 0; k < 8; k++) c[k] = fetch_corner(pk, ind[k]);

        float hmean[2], y[2], x[2];
        #pragma unroll
        for (int j = 0; j < 2; j++) {
            float hs = 0.f, sy = 0.f, sx = 0.f;
            #pragma unroll
            for (int k = 0; k < 4; k++) {
                hs += c[j * 4 + k].x;
                sy += c[j * 4 + k].y;
                sx += c[j * 4 + k].z;
            }
            hmean[j] = hs * 0.25f;
            // mean of (off + OFFSETS): OFFSETS contributes +0.5 per channel
            y[j] = sy * 0.25f + 0.5f;
            x[j] = sx * 0.25f + 0.5f;
        }
        float2 po = __ldg(reinterpret_cast<const float2*>(pre_off) + gid);
        y[1] += po.x;
        x[1] += po.y;

        float v = iou_f(__expf(hmean[0]), y[0], x[0],
                        __expf(hmean[1]), y[1], x[1]);

        float lsum = 0.f, cnt = 0.f;
        if (mask_rep[gid]) { lsum = v; cnt = 1.0f; }
        block_reduce2(lsum, cnt, &g_acc[2], &g_acc[3]);
    } else {
        // ----------- attract: two items per thread, 2x4 packed gathers -----------
        int w = (blockIdx.x - REP_BLOCKS) * 256 + threadIdx.x;  // [0, B*NATT/2)
        int gid0 = 2 * w;
        int b = gid0 >> 12;                                     // / 4096
        const uint2* pk = g_pack + ((size_t)b << 16);

        const int4* ap = reinterpret_cast<const int4*>(attract) + gid0;
        int4 idxA = __ldg(ap);
        int4 idxB = __ldg(ap + 1);
        uint2 m2 = __ldg(reinterpret_cast<const uint2*>(mask_att) + w);

        float lsum = 0.f, cnt = 0.f;
        attract_item(pk, idxA, m2.x, lsum, cnt);
        attract_item(pk, idxB, m2.y, lsum, cnt);
        block_reduce2(lsum, cnt, &g_acc[0], &g_acc[1]);
    }

    // ---------------- last-block finalize + reset ----------------
    __threadfence();
    __shared__ bool s_last;
    if (threadIdx.x == 0) {
        unsigned int ticket = atomicAdd(&g_done, 1u);
        s_last = (ticket == (unsigned int)(TOT_BLOCKS - 1));
    }
    __syncthreads();
    if (s_last && threadIdx.x == 0) {
        double sa = g_acc[0], na = g_acc[1];
        double sr = g_acc[2], nr = g_acc[3];
        out[0] = (float)(sa / (na + 1e-4) + sr / (nr + 1e-4));
        g_acc[0] = 0.0; g_acc[1] = 0.0; g_acc[2] = 0.0; g_acc[3] = 0.0;
        __threadfence();
        g_done = 0u;
    }
}

extern "C" void kernel_launch(void* const* d_in, const int* in_sizes, int n_in,
                              void* d_out, int out_size) {
    const float* output_h    = (const float*)d_in[0];  // [64,1,256,256]
    const float* output_off  = (const float*)d_in[1];  // [64,2,256,256]
    // d_in[2], d_in[3]: target_h / target_off — unused by the reference
    const float* pre_off     = (const float*)d_in[4];  // [64,2048,2]
    const int*   attract     = (const int*)  d_in[5];  // [64,4096,4]
    const int*   repel       = (const int*)  d_in[6];  // [64,2048,2,4]
    const unsigned char* mask_attract = (const unsigned char*)d_in[7];  // [64,4096,4] bool
    const unsigned char* mask_repel   = (const unsigned char*)d_in[8];  // [64,2048,1] bool
    float* out = (float*)d_out;

    pack_kernel<<<PACK_BLOCKS, 256>>>(output_h, output_off);
    gather_kernel<<<TOT_BLOCKS, 256>>>(pre_off, attract, repel,
                                       mask_attract, mask_repel, out);
}